// round 10
// baseline (speedup 1.0000x reference)
#include <cuda_runtime.h>
#include <cuda_bf16.h>
#include <cuda_fp16.h>
#include <cstdint>
#include <cstddef>

#define B_ROWS 4096
#define DDIM   512
#define KN     16384
#define NGRP   (KN / 8)      // 2048 8-col groups per row
#define NDT    (DDIM / 32)   // 16 d-tiles in transw
#define EPSV   1e-6f
#define DELTA  4.0f

// ---------------- device scratch (no allocation allowed) ----------------
__device__ __nv_bfloat16 gXb[(size_t)B_ROWS * DDIM];   // X bf16 row-major (b,d)
__device__ __nv_bfloat16 gWt[(size_t)KN * DDIM];       // W^T bf16 row-major (n,d)
__device__ float         gWt32[(size_t)KN * DDIM];     // W^T fp32 (n,d) for refine
__device__ __half        gGmin[(size_t)B_ROWS * NGRP]; // per-(row, 8col-group) d2 min
__device__ float         g_cp1[NDT * KN];              // col partial sums (per d-tile)
__device__ float         g_cp2[NDT * KN];              // col partial sumsq
__device__ float         g_c[KN];                      // exact col stats
__device__ float         g_r[B_ROWS];                  // exact row stats
__device__ float         g_dist[B_ROWS];               // per-row exact min dist

// ---------------- helpers ----------------
__device__ __forceinline__ uint32_t smem_u32(const void* p) {
    uint32_t a;
    asm("{ .reg .u64 t; cvta.to.shared.u64 t, %1; cvt.u32.u64 %0, t; }" : "=r"(a) : "l"(p));
    return a;
}
__device__ __forceinline__ void cpa16(uint32_t dst, const void* src) {
    asm volatile("cp.async.cg.shared.global [%0], [%1], 16;\n" :: "r"(dst), "l"(src));
}
#define CP_COMMIT() asm volatile("cp.async.commit_group;\n" ::: "memory")
#define CP_WAIT(n)  asm volatile("cp.async.wait_group %0;\n" :: "n"(n) : "memory")

__device__ __forceinline__ void ldsm_x4(uint32_t addr, uint32_t r[4]) {
    asm volatile("ldmatrix.sync.aligned.m8n8.x4.shared.b16 {%0,%1,%2,%3}, [%4];"
        : "=r"(r[0]), "=r"(r[1]), "=r"(r[2]), "=r"(r[3]) : "r"(addr));
}
__device__ __forceinline__ void mma_bf16(float c[4], const uint32_t a[4],
                                         uint32_t b0, uint32_t b1) {
    asm volatile("mma.sync.aligned.m16n8k16.row.col.f32.bf16.bf16.f32 "
        "{%0,%1,%2,%3}, {%4,%5,%6,%7}, {%8,%9}, {%0,%1,%2,%3};"
        : "+f"(c[0]), "+f"(c[1]), "+f"(c[2]), "+f"(c[3])
        : "r"(a[0]), "r"(a[1]), "r"(a[2]), "r"(a[3]), "r"(b0), "r"(b1));
}

// ---------------- prep kernels ----------------
// fused: X -> bf16 + exact row stats (single pass over X)
__global__ void prep_x_kernel(const float* __restrict__ X) {
    int b = blockIdx.x, t = threadIdx.x;
    float4 v = ((const float4*)(X + (size_t)b * DDIM))[t];
    __nv_bfloat162* xb = (__nv_bfloat162*)(gXb + (size_t)b * DDIM);
    xb[2 * t]     = __floats2bfloat162_rn(v.x, v.y);
    xb[2 * t + 1] = __floats2bfloat162_rn(v.z, v.w);
    float s = v.x + v.y + v.z + v.w;
    float s2 = v.x * v.x + v.y * v.y + v.z * v.z + v.w * v.w;
    #pragma unroll
    for (int o = 16; o; o >>= 1) {
        s  += __shfl_xor_sync(0xFFFFFFFFu, s,  o);
        s2 += __shfl_xor_sync(0xFFFFFFFFu, s2, o);
    }
    __shared__ float sh[8];
    int w = t >> 5;
    if ((t & 31) == 0) { sh[w] = s; sh[4 + w] = s2; }
    __syncthreads();
    if (t == 0) {
        float S = sh[0] + sh[1] + sh[2] + sh[3];
        float S2 = sh[4] + sh[5] + sh[6] + sh[7];
        g_r[b] = S2 + 2.f * EPSV * S + (float)DDIM * EPSV * EPSV;
    }
}

// fused: W transpose (fp32 + bf16 copies) + per-d-tile column partial stats
__global__ void transw_kernel(const float* __restrict__ W) {
    __shared__ float t[32][33];
    __shared__ float ps[8][32], ps2[8][32];
    int x = blockIdx.x * 32 + threadIdx.x;  // n
    int y = blockIdx.y * 32 + threadIdx.y;  // d
    #pragma unroll
    for (int j = 0; j < 32; j += 8)
        t[threadIdx.y + j][threadIdx.x] = W[(size_t)(y + j) * KN + x];
    __syncthreads();
    int nx = blockIdx.y * 32 + threadIdx.x;  // d
    int ny = blockIdx.x * 32 + threadIdx.y;  // n
    #pragma unroll
    for (int j = 0; j < 32; j += 8) {
        float v = t[threadIdx.x][threadIdx.y + j];
        gWt32[(size_t)(ny + j) * DDIM + nx] = v;
        gWt[(size_t)(ny + j) * DDIM + nx] = __float2bfloat16(v);
    }
    // per-column (n = x) partial sums over this 32-d tile, fixed order
    float s = 0.f, s2 = 0.f;
    #pragma unroll
    for (int j = 0; j < 4; ++j) {
        float w = t[threadIdx.y + j * 8][threadIdx.x];
        s += w;
        s2 = fmaf(w, w, s2);
    }
    ps[threadIdx.y][threadIdx.x] = s;
    ps2[threadIdx.y][threadIdx.x] = s2;
    __syncthreads();
    if (threadIdx.y == 0) {
        float S = 0.f, S2 = 0.f;
        #pragma unroll
        for (int j = 0; j < 8; ++j) { S += ps[j][threadIdx.x]; S2 += ps2[j][threadIdx.x]; }
        g_cp1[blockIdx.y * KN + blockIdx.x * 32 + threadIdx.x] = S;
        g_cp2[blockIdx.y * KN + blockIdx.x * 32 + threadIdx.x] = S2;
    }
}

__global__ void col_finalize_kernel() {
    int k = blockIdx.x * blockDim.x + threadIdx.x;
    if (k >= KN) return;
    float s = 0.f, s2 = 0.f;
    #pragma unroll
    for (int j = 0; j < NDT; ++j) { s += g_cp1[j * KN + k]; s2 += g_cp2[j * KN + k]; }
    g_c[k] = s2 - 2.f * EPSV * s;
}

// ------- bf16 mma.sync GEMM, 128x256 tile, Kc=64, double-buffered --------
//   0    : sCol (256 f32)  1024 : sRow (128 f32)
//   2048 : A0 16KB  18432: A1  34816: B0 32KB  67584: B1  -> 100352
#define SM_COL   0
#define SM_ROW   1024
#define SM_A0    2048
#define SM_A1    18432
#define SM_B0    34816
#define SM_B1    67584
#define SMEM_TOT 100352

__global__ void __launch_bounds__(256, 1)
gemm_kernel() {
    extern __shared__ char smem[];
    const uint32_t sb = smem_u32(smem);
    const int tid  = threadIdx.x;
    const int wid  = tid >> 5;
    const int lane = tid & 31;
    const int wm = wid >> 2;        // 0..1  (64 rows each)
    const int wn = wid & 3;         // 0..3  (64 cols each)
    const int rowBase = blockIdx.y * 128;
    const int colBase = blockIdx.x * 256;

    float* sCol = (float*)(smem + SM_COL);
    float* sRow = (float*)(smem + SM_ROW);

    sCol[tid] = g_c[colBase + tid];
    if (tid < 128) sRow[tid] = g_r[rowBase + tid];

    const uint32_t offA[2] = {SM_A0, SM_A1};
    const uint32_t offB[2] = {SM_B0, SM_B1};

    auto load_chunk = [&](int c) {
        const int buf = c & 1;
        const char* As = (const char*)(gXb + (size_t)rowBase * DDIM) + c * 128;
        const char* Bs = (const char*)(gWt + (size_t)colBase * DDIM) + c * 128;
        #pragma unroll
        for (int i = 0; i < 4; ++i) {   // A: 128 rows x 8 granules
            int g = tid + i * 256;
            int r = g >> 3, gi = g & 7;
            uint32_t d = r * 128 + ((gi * 16) ^ ((r & 7) << 4));
            cpa16(sb + offA[buf] + d, As + (size_t)r * 1024 + gi * 16);
        }
        #pragma unroll
        for (int i = 0; i < 8; ++i) {   // B: 256 rows x 8 granules
            int g = tid + i * 256;
            int n = g >> 3, gi = g & 7;
            uint32_t d = n * 128 + ((gi * 16) ^ ((n & 7) << 4));
            cpa16(sb + offB[buf] + d, Bs + (size_t)n * 1024 + gi * 16);
        }
        CP_COMMIT();
    };

    uint32_t baseA[4], patA[4];
    #pragma unroll
    for (int mi = 0; mi < 4; ++mi) {
        int r = wm * 64 + mi * 16 + (lane & 15);
        baseA[mi] = r * 128;
        patA[mi]  = (r & 7) << 4;
    }
    const uint32_t aQuad = (lane >> 4) * 16;
    uint32_t baseB[4], patB[4];
    #pragma unroll
    for (int bi = 0; bi < 4; ++bi) {
        int n = wn * 64 + bi * 16 + (lane & 7) + ((lane >> 4) << 3);
        baseB[bi] = n * 128;
        patB[bi]  = (n & 7) << 4;
    }
    const uint32_t bQuad = ((lane >> 3) & 1) * 16;

    float acc[4][8][4];
    #pragma unroll
    for (int a = 0; a < 4; ++a)
        #pragma unroll
        for (int b = 0; b < 8; ++b)
            #pragma unroll
            for (int q = 0; q < 4; ++q) acc[a][b][q] = 0.f;

    load_chunk(0);

    for (int c = 0; c < 8; ++c) {
        if (c + 1 < 8) { load_chunk(c + 1); CP_WAIT(1); }
        else           { CP_WAIT(0); }
        __syncthreads();

        const uint32_t aBuf = sb + offA[c & 1];
        const uint32_t bBuf = sb + offB[c & 1];
        #pragma unroll
        for (int kk = 0; kk < 4; ++kk) {
            const uint32_t kb = kk * 32;
            uint32_t af[4][4], bf[4][4];
            #pragma unroll
            for (int mi = 0; mi < 4; ++mi)
                ldsm_x4(aBuf + baseA[mi] + ((kb + aQuad) ^ patA[mi]), af[mi]);
            #pragma unroll
            for (int bi = 0; bi < 4; ++bi)
                ldsm_x4(bBuf + baseB[bi] + ((kb + bQuad) ^ patB[bi]), bf[bi]);
            #pragma unroll
            for (int mi = 0; mi < 4; ++mi)
                #pragma unroll
                for (int bi = 0; bi < 4; ++bi) {
                    mma_bf16(acc[mi][bi * 2 + 0], af[mi], bf[bi][0], bf[bi][1]);
                    mma_bf16(acc[mi][bi * 2 + 1], af[mi], bf[bi][2], bf[bi][3]);
                }
        }
        __syncthreads();
    }

    // ---- epilogue: per-(row, 8col-group) d2 mins -> gGmin ----
    const int tig = lane & 3;
    const int g   = lane >> 2;
    const int gcolb = blockIdx.x * 32 + wn * 8;
    #pragma unroll
    for (int mi = 0; mi < 4; ++mi) {
        const int r0 = wm * 64 + mi * 16 + g;
        const int r1 = r0 + 8;
        const float rr0 = sRow[r0], rr1 = sRow[r1];
        float gm0[8], gm1[8];
        #pragma unroll
        for (int j = 0; j < 8; ++j) {
            const int cb = wn * 64 + j * 8 + 2 * tig;
            const float cc0 = sCol[cb], cc1 = sCol[cb + 1];
            float m0 = fminf(rr0 + cc0 - 2.f * acc[mi][j][0],
                             rr0 + cc1 - 2.f * acc[mi][j][1]);
            float m1 = fminf(rr1 + cc0 - 2.f * acc[mi][j][2],
                             rr1 + cc1 - 2.f * acc[mi][j][3]);
            m0 = fminf(m0, __shfl_xor_sync(0xFFFFFFFFu, m0, 1));
            m0 = fminf(m0, __shfl_xor_sync(0xFFFFFFFFu, m0, 2));
            m1 = fminf(m1, __shfl_xor_sync(0xFFFFFFFFu, m1, 1));
            m1 = fminf(m1, __shfl_xor_sync(0xFFFFFFFFu, m1, 2));
            gm0[j] = m0;
            gm1[j] = m1;
        }
        if (tig == 0) {
            __half2 a0 = __floats2half2_rn(gm0[0], gm0[1]);
            __half2 a1 = __floats2half2_rn(gm0[2], gm0[3]);
            __half2 a2 = __floats2half2_rn(gm0[4], gm0[5]);
            __half2 a3 = __floats2half2_rn(gm0[6], gm0[7]);
            __half2 b0 = __floats2half2_rn(gm1[0], gm1[1]);
            __half2 b1 = __floats2half2_rn(gm1[2], gm1[3]);
            __half2 b2 = __floats2half2_rn(gm1[4], gm1[5]);
            __half2 b3 = __floats2half2_rn(gm1[6], gm1[7]);
            uint4 v0, v1;
            v0.x = *(uint32_t*)&a0; v0.y = *(uint32_t*)&a1;
            v0.z = *(uint32_t*)&a2; v0.w = *(uint32_t*)&a3;
            v1.x = *(uint32_t*)&b0; v1.y = *(uint32_t*)&b1;
            v1.z = *(uint32_t*)&b2; v1.w = *(uint32_t*)&b3;
            *(uint4*)(gGmin + (size_t)(rowBase + r0) * NGRP + gcolb) = v0;
            *(uint4*)(gGmin + (size_t)(rowBase + r1) * NGRP + gcolb) = v1;
        }
    }
}

// ------- refine: group-min scan -> qualifying groups -> exact fp32 dots -------
__global__ void refine_kernel(const float* __restrict__ X,
                              const float* __restrict__ loc,
                              float* __restrict__ out, int out_size) {
    const int b = blockIdx.x;
    const int tid = threadIdx.x;
    const int wid = tid >> 5;
    const int lane = tid & 31;
    __shared__ unsigned sMin;
    __shared__ int cnt;
    __shared__ int grp[256];
    __shared__ unsigned long long wbest[8];
    if (tid == 0) { sMin = 0x7F800000u; cnt = 0; }
    __syncthreads();

    const uint4 v = ((const uint4*)(gGmin + (size_t)b * NGRP))[tid];
    const uint32_t ww[4] = {v.x, v.y, v.z, v.w};
    float h[8];
    #pragma unroll
    for (int q = 0; q < 4; ++q) {
        __half2 p = *(const __half2*)&ww[q];
        h[2 * q]     = __low2float(p);
        h[2 * q + 1] = __high2float(p);
    }
    float m = h[0];
    #pragma unroll
    for (int q = 1; q < 8; ++q) m = fminf(m, h[q]);
    #pragma unroll
    for (int o = 16; o; o >>= 1) m = fminf(m, __shfl_sync(0xFFFFFFFFu, m, lane ^ o));
    if (lane == 0) atomicMin(&sMin, __float_as_uint(m));
    __syncthreads();

    const float thr = __uint_as_float(sMin) + DELTA;
    #pragma unroll
    for (int q = 0; q < 8; ++q)
        if (h[q] <= thr) { int p = atomicAdd(&cnt, 1); if (p < 256) grp[p] = tid * 8 + q; }
    __syncthreads();
    const int ng = min(cnt, 256);
    const int ncand = ng * 8;

    const float4* xr = (const float4*)(X + (size_t)b * DDIM);
    float4 xv[4];
    #pragma unroll
    for (int i = 0; i < 4; ++i) xv[i] = xr[i * 32 + lane];

    unsigned long long best = 0xFFFFFFFFFFFFFFFFULL;
    for (int ci = wid; ci < ncand; ci += 8) {
        const int k = grp[ci >> 3] * 8 + (ci & 7);
        const float4* wr = (const float4*)(gWt32 + (size_t)k * DDIM);
        float s = 0.f;
        #pragma unroll
        for (int i = 0; i < 4; ++i) {
            float4 w = wr[i * 32 + lane];
            s = fmaf(xv[i].x, w.x, s);
            s = fmaf(xv[i].y, w.y, s);
            s = fmaf(xv[i].z, w.z, s);
            s = fmaf(xv[i].w, w.w, s);
        }
        #pragma unroll
        for (int o = 16; o; o >>= 1) s += __shfl_xor_sync(0xFFFFFFFFu, s, o);
        if (lane == 0) {
            float d2 = g_r[b] + g_c[k] - 2.f * s;
            unsigned u = __float_as_uint(d2);
            u = (u & 0x80000000u) ? ~u : (u | 0x80000000u);
            unsigned long long key = ((unsigned long long)u << 32) | (unsigned)k;
            if (key < best) best = key;
        }
    }
    if (lane == 0) wbest[wid] = best;
    __syncthreads();

    if (tid == 0) {
        unsigned long long bb = 0xFFFFFFFFFFFFFFFFULL;
        #pragma unroll
        for (int w = 0; w < 8; ++w) if (wbest[w] < bb) bb = wbest[w];
        unsigned k = (unsigned)(bb & 0xFFFFFFFFu);
        unsigned u = (unsigned)(bb >> 32);
        u = (u & 0x80000000u) ? (u & 0x7FFFFFFFu) : ~u;
        float d2 = __uint_as_float(u);
        g_dist[b] = sqrtf(fmaxf(d2, 0.f));
        out[2 * b] = loc[2 * k];
        if (2 * b + 1 < out_size - 1) out[2 * b + 1] = loc[2 * k + 1];
    }
}

__global__ void loss_kernel(float* __restrict__ out, int out_size) {
    __shared__ float sh[1024];
    float local = 0.f;
    for (int b = threadIdx.x; b < B_ROWS; b += 1024) local += g_dist[b];
    sh[threadIdx.x] = local;
    __syncthreads();
    #pragma unroll
    for (int s = 512; s > 0; s >>= 1) {
        if (threadIdx.x < s) sh[threadIdx.x] += sh[threadIdx.x + s];
        __syncthreads();
    }
    if (threadIdx.x == 0) out[out_size - 1] = sh[0] / (float)B_ROWS;
}

// ---------------------------------------------------------------------------
extern "C" void kernel_launch(void* const* d_in, const int* in_sizes, int n_in,
                              void* d_out, int out_size) {
    const float* X = (const float*)d_in[0];  // (4096, 512)
    const float* W = (const float*)d_in[1];  // (512, 16384)
    const float* L = (const float*)d_in[2];  // (16384, 2)
    float* out = (float*)d_out;

    cudaFuncSetAttribute(gemm_kernel, cudaFuncAttributeMaxDynamicSharedMemorySize, SMEM_TOT);

    prep_x_kernel<<<B_ROWS, 128>>>(X);
    transw_kernel<<<dim3(KN / 32, DDIM / 32), dim3(32, 8)>>>(W);
    col_finalize_kernel<<<KN / 256, 256>>>();

    gemm_kernel<<<dim3(KN / 256, B_ROWS / 128), 256, SMEM_TOT>>>();

    refine_kernel<<<B_ROWS, 256>>>(X, L, out, out_size);
    loss_kernel<<<1, 1024>>>(out, out_size);
}

// round 11
// speedup vs baseline: 1.1174x; 1.1174x over previous
#include <cuda_runtime.h>
#include <cuda_bf16.h>
#include <cuda_fp16.h>
#include <cstdint>
#include <cstddef>

#define B_ROWS 4096
#define DDIM   512
#define KN     16384
#define NGRP   (KN / 8)      // 2048 8-col groups per row
#define NDT    (DDIM / 32)   // 16 d-tiles in transw
#define EPSV   1e-6f
#define DELTA  4.0f

// ---------------- device scratch (no allocation allowed) ----------------
__device__ __nv_bfloat16 gXb[(size_t)B_ROWS * DDIM];   // X bf16 row-major (b,d)
__device__ __nv_bfloat16 gWt[(size_t)KN * DDIM];       // W^T bf16 row-major (n,d)
__device__ float         gWt32[(size_t)KN * DDIM];     // W^T fp32 (n,d) for refine
__device__ __half        gGmin[(size_t)B_ROWS * NGRP]; // per-(row, 8col-group) d2 min
__device__ float         g_cp1[NDT * KN];              // col partial sums (per d-tile)
__device__ float         g_cp2[NDT * KN];              // col partial sumsq
__device__ float         g_c[KN];                      // exact col stats
__device__ float         g_r[B_ROWS];                  // exact row stats
__device__ float         g_dist[B_ROWS];               // per-row exact min dist

// ---------------- helpers ----------------
__device__ __forceinline__ uint32_t smem_u32(const void* p) {
    uint32_t a;
    asm("{ .reg .u64 t; cvta.to.shared.u64 t, %1; cvt.u32.u64 %0, t; }" : "=r"(a) : "l"(p));
    return a;
}
__device__ __forceinline__ void cpa16(uint32_t dst, const void* src) {
    asm volatile("cp.async.cg.shared.global [%0], [%1], 16;\n" :: "r"(dst), "l"(src));
}
#define CP_COMMIT() asm volatile("cp.async.commit_group;\n" ::: "memory")
#define CP_WAIT(n)  asm volatile("cp.async.wait_group %0;\n" :: "n"(n) : "memory")

__device__ __forceinline__ void ldsm_x4(uint32_t addr, uint32_t r[4]) {
    asm volatile("ldmatrix.sync.aligned.m8n8.x4.shared.b16 {%0,%1,%2,%3}, [%4];"
        : "=r"(r[0]), "=r"(r[1]), "=r"(r[2]), "=r"(r[3]) : "r"(addr));
}
__device__ __forceinline__ void mma_bf16(float c[4], const uint32_t a[4],
                                         uint32_t b0, uint32_t b1) {
    asm volatile("mma.sync.aligned.m16n8k16.row.col.f32.bf16.bf16.f32 "
        "{%0,%1,%2,%3}, {%4,%5,%6,%7}, {%8,%9}, {%0,%1,%2,%3};"
        : "+f"(c[0]), "+f"(c[1]), "+f"(c[2]), "+f"(c[3])
        : "r"(a[0]), "r"(a[1]), "r"(a[2]), "r"(a[3]), "r"(b0), "r"(b1));
}

// ---------------- prep kernels ----------------
// fused: X -> bf16 + exact row stats (single pass over X)
__global__ void prep_x_kernel(const float* __restrict__ X) {
    int b = blockIdx.x, t = threadIdx.x;
    float4 v = ((const float4*)(X + (size_t)b * DDIM))[t];
    __nv_bfloat162* xb = (__nv_bfloat162*)(gXb + (size_t)b * DDIM);
    xb[2 * t]     = __floats2bfloat162_rn(v.x, v.y);
    xb[2 * t + 1] = __floats2bfloat162_rn(v.z, v.w);
    float s = v.x + v.y + v.z + v.w;
    float s2 = v.x * v.x + v.y * v.y + v.z * v.z + v.w * v.w;
    #pragma unroll
    for (int o = 16; o; o >>= 1) {
        s  += __shfl_xor_sync(0xFFFFFFFFu, s,  o);
        s2 += __shfl_xor_sync(0xFFFFFFFFu, s2, o);
    }
    __shared__ float sh[8];
    int w = t >> 5;
    if ((t & 31) == 0) { sh[w] = s; sh[4 + w] = s2; }
    __syncthreads();
    if (t == 0) {
        float S = sh[0] + sh[1] + sh[2] + sh[3];
        float S2 = sh[4] + sh[5] + sh[6] + sh[7];
        g_r[b] = S2 + 2.f * EPSV * S + (float)DDIM * EPSV * EPSV;
    }
}

// fused: W transpose (fp32 + bf16 copies) + per-d-tile column partial stats
__global__ void transw_kernel(const float* __restrict__ W) {
    __shared__ float t[32][33];
    __shared__ float ps[8][32], ps2[8][32];
    int x = blockIdx.x * 32 + threadIdx.x;  // n
    int y = blockIdx.y * 32 + threadIdx.y;  // d
    #pragma unroll
    for (int j = 0; j < 32; j += 8)
        t[threadIdx.y + j][threadIdx.x] = W[(size_t)(y + j) * KN + x];
    __syncthreads();
    int nx = blockIdx.y * 32 + threadIdx.x;  // d
    int ny = blockIdx.x * 32 + threadIdx.y;  // n
    #pragma unroll
    for (int j = 0; j < 32; j += 8) {
        float v = t[threadIdx.x][threadIdx.y + j];
        gWt32[(size_t)(ny + j) * DDIM + nx] = v;
        gWt[(size_t)(ny + j) * DDIM + nx] = __float2bfloat16(v);
    }
    float s = 0.f, s2 = 0.f;
    #pragma unroll
    for (int j = 0; j < 4; ++j) {
        float w = t[threadIdx.y + j * 8][threadIdx.x];
        s += w;
        s2 = fmaf(w, w, s2);
    }
    ps[threadIdx.y][threadIdx.x] = s;
    ps2[threadIdx.y][threadIdx.x] = s2;
    __syncthreads();
    if (threadIdx.y == 0) {
        float S = 0.f, S2 = 0.f;
        #pragma unroll
        for (int j = 0; j < 8; ++j) { S += ps[j][threadIdx.x]; S2 += ps2[j][threadIdx.x]; }
        g_cp1[blockIdx.y * KN + blockIdx.x * 32 + threadIdx.x] = S;
        g_cp2[blockIdx.y * KN + blockIdx.x * 32 + threadIdx.x] = S2;
    }
}

__global__ void col_finalize_kernel() {
    int k = blockIdx.x * blockDim.x + threadIdx.x;
    if (k >= KN) return;
    float s = 0.f, s2 = 0.f;
    #pragma unroll
    for (int j = 0; j < NDT; ++j) { s += g_cp1[j * KN + k]; s2 += g_cp2[j * KN + k]; }
    g_c[k] = s2 - 2.f * EPSV * s;
}

// ---------------- bf16 mma.sync GEMM, 128x128 tile, Kc=64, dbl-buffered ------
#define SM_COL   0
#define SM_ROW   512
#define SM_A0    2048
#define SM_A1    18432
#define SM_B0    34816
#define SM_B1    51200
#define SMEM_TOT 67584

__global__ void __launch_bounds__(256, 2)
gemm_kernel() {
    extern __shared__ char smem[];
    const uint32_t sb = smem_u32(smem);
    const int tid  = threadIdx.x;
    const int wid  = tid >> 5;
    const int lane = tid & 31;
    const int wm = wid >> 2;        // 0..1  (64 rows each)
    const int wn = wid & 3;         // 0..3  (32 cols each)
    const int rowBase = blockIdx.y * 128;
    const int colBase = blockIdx.x * 128;

    float* sCol = (float*)(smem + SM_COL);
    float* sRow = (float*)(smem + SM_ROW);

    if (tid < 128) {
        sCol[tid] = g_c[colBase + tid];
        sRow[tid] = g_r[rowBase + tid];
    }

    const uint32_t offA[2] = {SM_A0, SM_A1};
    const uint32_t offB[2] = {SM_B0, SM_B1};

    auto load_chunk = [&](int c) {
        const int buf = c & 1;
        const char* As = (const char*)(gXb + (size_t)rowBase * DDIM) + c * 128;
        const char* Bs = (const char*)(gWt + (size_t)colBase * DDIM) + c * 128;
        #pragma unroll
        for (int i = 0; i < 4; ++i) {
            int g = tid + i * 256;
            int r = g >> 3, gi = g & 7;
            uint32_t d = r * 128 + ((gi * 16) ^ ((r & 7) << 4));
            cpa16(sb + offA[buf] + d, As + (size_t)r * 1024 + gi * 16);
        }
        #pragma unroll
        for (int i = 0; i < 4; ++i) {
            int g = tid + i * 256;
            int n = g >> 3, gi = g & 7;
            uint32_t d = n * 128 + ((gi * 16) ^ ((n & 7) << 4));
            cpa16(sb + offB[buf] + d, Bs + (size_t)n * 1024 + gi * 16);
        }
        CP_COMMIT();
    };

    uint32_t baseA[4], patA[4];
    #pragma unroll
    for (int mi = 0; mi < 4; ++mi) {
        int r = wm * 64 + mi * 16 + (lane & 15);
        baseA[mi] = r * 128;
        patA[mi]  = (r & 7) << 4;
    }
    const uint32_t aQuad = (lane >> 4) * 16;
    uint32_t baseB[2], patB[2];
    #pragma unroll
    for (int bi = 0; bi < 2; ++bi) {
        int n = wn * 32 + bi * 16 + (lane & 7) + ((lane >> 4) << 3);
        baseB[bi] = n * 128;
        patB[bi]  = (n & 7) << 4;
    }
    const uint32_t bQuad = ((lane >> 3) & 1) * 16;

    float acc[4][4][4];
    #pragma unroll
    for (int a = 0; a < 4; ++a)
        #pragma unroll
        for (int b = 0; b < 4; ++b)
            #pragma unroll
            for (int q = 0; q < 4; ++q) acc[a][b][q] = 0.f;

    load_chunk(0);

    for (int c = 0; c < 8; ++c) {
        if (c + 1 < 8) { load_chunk(c + 1); CP_WAIT(1); }
        else           { CP_WAIT(0); }
        __syncthreads();

        const uint32_t aBuf = sb + offA[c & 1];
        const uint32_t bBuf = sb + offB[c & 1];
        #pragma unroll
        for (int kk = 0; kk < 4; ++kk) {
            const uint32_t kb = kk * 32;
            uint32_t af[4][4], bf[2][4];
            #pragma unroll
            for (int mi = 0; mi < 4; ++mi)
                ldsm_x4(aBuf + baseA[mi] + ((kb + aQuad) ^ patA[mi]), af[mi]);
            #pragma unroll
            for (int bi = 0; bi < 2; ++bi)
                ldsm_x4(bBuf + baseB[bi] + ((kb + bQuad) ^ patB[bi]), bf[bi]);
            #pragma unroll
            for (int mi = 0; mi < 4; ++mi)
                #pragma unroll
                for (int bi = 0; bi < 2; ++bi) {
                    mma_bf16(acc[mi][bi * 2 + 0], af[mi], bf[bi][0], bf[bi][1]);
                    mma_bf16(acc[mi][bi * 2 + 1], af[mi], bf[bi][2], bf[bi][3]);
                }
        }
        __syncthreads();
    }

    // ---- epilogue: per-(row, 8col-group) d2 mins -> gGmin ----
    const int tig = lane & 3;
    const int g   = lane >> 2;
    float gm0[4][4], gm1[4][4];
    #pragma unroll
    for (int mi = 0; mi < 4; ++mi) {
        const int r0 = wm * 64 + mi * 16 + g;
        const int r1 = r0 + 8;
        const float rr0 = sRow[r0], rr1 = sRow[r1];
        #pragma unroll
        for (int j = 0; j < 4; ++j) {
            const int cb = wn * 32 + j * 8 + 2 * tig;
            const float cc0 = sCol[cb], cc1 = sCol[cb + 1];
            float m0 = fminf(rr0 + cc0 - 2.f * acc[mi][j][0],
                             rr0 + cc1 - 2.f * acc[mi][j][1]);
            float m1 = fminf(rr1 + cc0 - 2.f * acc[mi][j][2],
                             rr1 + cc1 - 2.f * acc[mi][j][3]);
            m0 = fminf(m0, __shfl_xor_sync(0xFFFFFFFFu, m0, 1));
            m0 = fminf(m0, __shfl_xor_sync(0xFFFFFFFFu, m0, 2));
            m1 = fminf(m1, __shfl_xor_sync(0xFFFFFFFFu, m1, 1));
            m1 = fminf(m1, __shfl_xor_sync(0xFFFFFFFFu, m1, 2));
            gm0[mi][j] = m0;
            gm1[mi][j] = m1;
        }
    }
    if (tig == 0) {
        const int gcol = blockIdx.x * 16 + wn * 4;
        #pragma unroll
        for (int mi = 0; mi < 4; ++mi) {
            const int r0 = rowBase + wm * 64 + mi * 16 + g;
            const int r1 = r0 + 8;
            __half2 a0 = __floats2half2_rn(gm0[mi][0], gm0[mi][1]);
            __half2 a1 = __floats2half2_rn(gm0[mi][2], gm0[mi][3]);
            __half2 b0 = __floats2half2_rn(gm1[mi][0], gm1[mi][1]);
            __half2 b1 = __floats2half2_rn(gm1[mi][2], gm1[mi][3]);
            uint2 v0, v1;
            v0.x = *(uint32_t*)&a0; v0.y = *(uint32_t*)&a1;
            v1.x = *(uint32_t*)&b0; v1.y = *(uint32_t*)&b1;
            *(uint2*)(gGmin + (size_t)r0 * NGRP + gcol) = v0;
            *(uint2*)(gGmin + (size_t)r1 * NGRP + gcol) = v1;
        }
    }
}

// ------- refine: group-min scan -> qualifying groups -> exact fp32 dots -------
__global__ void refine_kernel(const float* __restrict__ X,
                              const float* __restrict__ loc,
                              float* __restrict__ out, int out_size) {
    const int b = blockIdx.x;
    const int tid = threadIdx.x;
    const int wid = tid >> 5;
    const int lane = tid & 31;
    __shared__ unsigned sMin;
    __shared__ int cnt;
    __shared__ int grp[256];
    __shared__ unsigned long long wbest[8];
    if (tid == 0) { sMin = 0x7F800000u; cnt = 0; }
    __syncthreads();

    const uint4 v = ((const uint4*)(gGmin + (size_t)b * NGRP))[tid];
    const uint32_t ww[4] = {v.x, v.y, v.z, v.w};
    float h[8];
    #pragma unroll
    for (int q = 0; q < 4; ++q) {
        __half2 p = *(const __half2*)&ww[q];
        h[2 * q]     = __low2float(p);
        h[2 * q + 1] = __high2float(p);
    }
    float m = h[0];
    #pragma unroll
    for (int q = 1; q < 8; ++q) m = fminf(m, h[q]);
    #pragma unroll
    for (int o = 16; o; o >>= 1) m = fminf(m, __shfl_sync(0xFFFFFFFFu, m, lane ^ o));
    if (lane == 0) atomicMin(&sMin, __float_as_uint(m));
    __syncthreads();

    const float thr = __uint_as_float(sMin) + DELTA;
    #pragma unroll
    for (int q = 0; q < 8; ++q)
        if (h[q] <= thr) { int p = atomicAdd(&cnt, 1); if (p < 256) grp[p] = tid * 8 + q; }
    __syncthreads();
    const int ng = min(cnt, 256);
    const int ncand = ng * 8;

    const float4* xr = (const float4*)(X + (size_t)b * DDIM);
    float4 xv[4];
    #pragma unroll
    for (int i = 0; i < 4; ++i) xv[i] = xr[i * 32 + lane];

    unsigned long long best = 0xFFFFFFFFFFFFFFFFULL;
    for (int ci = wid; ci < ncand; ci += 8) {
        const int k = grp[ci >> 3] * 8 + (ci & 7);
        const float4* wr = (const float4*)(gWt32 + (size_t)k * DDIM);
        float s = 0.f;
        #pragma unroll
        for (int i = 0; i < 4; ++i) {
            float4 w = wr[i * 32 + lane];
            s = fmaf(xv[i].x, w.x, s);
            s = fmaf(xv[i].y, w.y, s);
            s = fmaf(xv[i].z, w.z, s);
            s = fmaf(xv[i].w, w.w, s);
        }
        #pragma unroll
        for (int o = 16; o; o >>= 1) s += __shfl_xor_sync(0xFFFFFFFFu, s, o);
        if (lane == 0) {
            float d2 = g_r[b] + g_c[k] - 2.f * s;
            unsigned u = __float_as_uint(d2);
            u = (u & 0x80000000u) ? ~u : (u | 0x80000000u);
            unsigned long long key = ((unsigned long long)u << 32) | (unsigned)k;
            if (key < best) best = key;
        }
    }
    if (lane == 0) wbest[wid] = best;
    __syncthreads();

    if (tid == 0) {
        unsigned long long bb = 0xFFFFFFFFFFFFFFFFULL;
        #pragma unroll
        for (int w = 0; w < 8; ++w) if (wbest[w] < bb) bb = wbest[w];
        unsigned k = (unsigned)(bb & 0xFFFFFFFFu);
        unsigned u = (unsigned)(bb >> 32);
        u = (u & 0x80000000u) ? (u & 0x7FFFFFFFu) : ~u;
        float d2 = __uint_as_float(u);
        g_dist[b] = sqrtf(fmaxf(d2, 0.f));
        out[2 * b] = loc[2 * k];
        if (2 * b + 1 < out_size - 1) out[2 * b + 1] = loc[2 * k + 1];
    }
}

__global__ void loss_kernel(float* __restrict__ out, int out_size) {
    __shared__ float sh[1024];
    float local = 0.f;
    for (int b = threadIdx.x; b < B_ROWS; b += 1024) local += g_dist[b];
    sh[threadIdx.x] = local;
    __syncthreads();
    #pragma unroll
    for (int s = 512; s > 0; s >>= 1) {
        if (threadIdx.x < s) sh[threadIdx.x] += sh[threadIdx.x + s];
        __syncthreads();
    }
    if (threadIdx.x == 0) out[out_size - 1] = sh[0] / (float)B_ROWS;
}

// ---------------------------------------------------------------------------
extern "C" void kernel_launch(void* const* d_in, const int* in_sizes, int n_in,
                              void* d_out, int out_size) {
    const float* X = (const float*)d_in[0];  // (4096, 512)
    const float* W = (const float*)d_in[1];  // (512, 16384)
    const float* L = (const float*)d_in[2];  // (16384, 2)
    float* out = (float*)d_out;

    cudaFuncSetAttribute(gemm_kernel, cudaFuncAttributeMaxDynamicSharedMemorySize, SMEM_TOT);

    prep_x_kernel<<<B_ROWS, 128>>>(X);
    transw_kernel<<<dim3(KN / 32, DDIM / 32), dim3(32, 8)>>>(W);
    col_finalize_kernel<<<KN / 256, 256>>>();

    gemm_kernel<<<dim3(KN / 128, B_ROWS / 128), 256, SMEM_TOT>>>();

    refine_kernel<<<B_ROWS, 256>>>(X, L, out, out_size);
    loss_kernel<<<1, 1024>>>(out, out_size);
}

// round 12
// speedup vs baseline: 1.2101x; 1.0830x over previous
#include <cuda_runtime.h>
#include <cuda_bf16.h>
#include <cuda_fp16.h>
#include <cstdint>
#include <cstddef>

#define B_ROWS 4096
#define DDIM   512
#define KN     16384
#define NGRP   (KN / 8)      // 2048 8-col groups per row
#define NDT    (DDIM / 32)   // 16 d-tiles in transw
#define EPSV   1e-6f
#define DELTA  4.0f

// ---------------- device scratch (no allocation allowed) ----------------
__device__ __nv_bfloat16 gXb[(size_t)B_ROWS * DDIM];   // X bf16 row-major (b,d)
__device__ __nv_bfloat16 gWt[(size_t)KN * DDIM];       // W^T bf16 row-major (n,d)
__device__ float         gWt32[(size_t)KN * DDIM];     // W^T fp32 (n,d) for refine
__device__ __half        gGmin[(size_t)B_ROWS * NGRP]; // per-(row, 8col-group) d2 min
__device__ float         g_cp1[NDT * KN];              // col partial sums (per d-tile)
__device__ float         g_cp2[NDT * KN];              // col partial sumsq
__device__ float         g_c[KN];                      // exact col stats
__device__ float         g_r[B_ROWS];                  // exact row stats
__device__ float         g_dist[B_ROWS];               // per-row exact min dist

// ---------------- helpers ----------------
__device__ __forceinline__ uint32_t smem_u32(const void* p) {
    uint32_t a;
    asm("{ .reg .u64 t; cvta.to.shared.u64 t, %1; cvt.u32.u64 %0, t; }" : "=r"(a) : "l"(p));
    return a;
}
__device__ __forceinline__ void cpa16(uint32_t dst, const void* src) {
    asm volatile("cp.async.cg.shared.global [%0], [%1], 16;\n" :: "r"(dst), "l"(src));
}
#define CP_COMMIT() asm volatile("cp.async.commit_group;\n" ::: "memory")
#define CP_WAIT(n)  asm volatile("cp.async.wait_group %0;\n" :: "n"(n) : "memory")

__device__ __forceinline__ void ldsm_x4(uint32_t addr, uint32_t r[4]) {
    asm volatile("ldmatrix.sync.aligned.m8n8.x4.shared.b16 {%0,%1,%2,%3}, [%4];"
        : "=r"(r[0]), "=r"(r[1]), "=r"(r[2]), "=r"(r[3]) : "r"(addr));
}
__device__ __forceinline__ void mma_bf16(float c[4], const uint32_t a[4],
                                         uint32_t b0, uint32_t b1) {
    asm volatile("mma.sync.aligned.m16n8k16.row.col.f32.bf16.bf16.f32 "
        "{%0,%1,%2,%3}, {%4,%5,%6,%7}, {%8,%9}, {%0,%1,%2,%3};"
        : "+f"(c[0]), "+f"(c[1]), "+f"(c[2]), "+f"(c[3])
        : "r"(a[0]), "r"(a[1]), "r"(a[2]), "r"(a[3]), "r"(b0), "r"(b1));
}

// ---------------- fused prep: blocks [0,8192) = W transpose+col partials,
// blocks [8192,10240) = X conv + row stats (2 rows per block) ----------------
__global__ void prep_kernel(const float* __restrict__ X, const float* __restrict__ W) {
    if (blockIdx.x < 8192) {
        // ---- transw part: bx in [0,512), by in [0,16) ----
        const int bx = blockIdx.x & 511;
        const int by = blockIdx.x >> 9;
        const int tx = threadIdx.x & 31;
        const int ty = threadIdx.x >> 5;   // 0..7
        __shared__ float t[32][33];
        __shared__ float ps[8][32], ps2[8][32];
        int x = bx * 32 + tx;  // n
        int y = by * 32 + ty;  // d
        #pragma unroll
        for (int j = 0; j < 32; j += 8)
            t[ty + j][tx] = W[(size_t)(y + j) * KN + x];
        __syncthreads();
        int nx = by * 32 + tx;  // d
        int ny = bx * 32 + ty;  // n
        #pragma unroll
        for (int j = 0; j < 32; j += 8) {
            float v = t[tx][ty + j];
            gWt32[(size_t)(ny + j) * DDIM + nx] = v;
            gWt[(size_t)(ny + j) * DDIM + nx] = __float2bfloat16(v);
        }
        float s = 0.f, s2 = 0.f;
        #pragma unroll
        for (int j = 0; j < 4; ++j) {
            float w = t[ty + j * 8][tx];
            s += w;
            s2 = fmaf(w, w, s2);
        }
        ps[ty][tx] = s;
        ps2[ty][tx] = s2;
        __syncthreads();
        if (ty == 0) {
            float S = 0.f, S2 = 0.f;
            #pragma unroll
            for (int j = 0; j < 8; ++j) { S += ps[j][tx]; S2 += ps2[j][tx]; }
            g_cp1[by * KN + bx * 32 + tx] = S;
            g_cp2[by * KN + bx * 32 + tx] = S2;
        }
    } else {
        // ---- prep_x part: 2 rows per block ----
        const int b = (blockIdx.x - 8192) * 2 + (threadIdx.x >> 7);
        const int t = threadIdx.x & 127;
        float4 v = ((const float4*)(X + (size_t)b * DDIM))[t];
        __nv_bfloat162* xb = (__nv_bfloat162*)(gXb + (size_t)b * DDIM);
        xb[2 * t]     = __floats2bfloat162_rn(v.x, v.y);
        xb[2 * t + 1] = __floats2bfloat162_rn(v.z, v.w);
        float s = v.x + v.y + v.z + v.w;
        float s2 = v.x * v.x + v.y * v.y + v.z * v.z + v.w * v.w;
        #pragma unroll
        for (int o = 16; o; o >>= 1) {
            s  += __shfl_xor_sync(0xFFFFFFFFu, s,  o);
            s2 += __shfl_xor_sync(0xFFFFFFFFu, s2, o);
        }
        __shared__ float sh[2][8];
        int sub = threadIdx.x >> 7;
        int w = (t >> 5);
        if ((t & 31) == 0) { sh[sub][w] = s; sh[sub][4 + w] = s2; }
        __syncthreads();
        if (t == 0) {
            float S = sh[sub][0] + sh[sub][1] + sh[sub][2] + sh[sub][3];
            float S2 = sh[sub][4] + sh[sub][5] + sh[sub][6] + sh[sub][7];
            g_r[b] = S2 + 2.f * EPSV * S + (float)DDIM * EPSV * EPSV;
        }
    }
}

__global__ void col_finalize_kernel() {
    int k = blockIdx.x * blockDim.x + threadIdx.x;
    if (k >= KN) return;
    float s = 0.f, s2 = 0.f;
    #pragma unroll
    for (int j = 0; j < NDT; ++j) { s += g_cp1[j * KN + k]; s2 += g_cp2[j * KN + k]; }
    g_c[k] = s2 - 2.f * EPSV * s;
}

// ---- bf16 mma.sync GEMM, 128x128 tile, Kc=64, 3-stage cp.async pipeline ----
#define SM_COL   0
#define SM_ROW   512
#define SM_A0    2048
#define SM_A1    18432
#define SM_A2    34816
#define SM_B0    51200
#define SM_B1    67584
#define SM_B2    83968
#define SMEM_TOT 100352

__global__ void __launch_bounds__(256, 2)
gemm_kernel() {
    extern __shared__ char smem[];
    const uint32_t sb = smem_u32(smem);
    const int tid  = threadIdx.x;
    const int wid  = tid >> 5;
    const int lane = tid & 31;
    const int wm = wid >> 2;        // 0..1  (64 rows each)
    const int wn = wid & 3;         // 0..3  (32 cols each)
    const int rowBase = blockIdx.y * 128;
    const int colBase = blockIdx.x * 128;

    float* sCol = (float*)(smem + SM_COL);
    float* sRow = (float*)(smem + SM_ROW);

    if (tid < 128) {
        sCol[tid] = g_c[colBase + tid];
        sRow[tid] = g_r[rowBase + tid];
    }

    const uint32_t offA[3] = {SM_A0, SM_A1, SM_A2};
    const uint32_t offB[3] = {SM_B0, SM_B1, SM_B2};

    auto load_chunk = [&](int c, int stg) {
        const char* As = (const char*)(gXb + (size_t)rowBase * DDIM) + c * 128;
        const char* Bs = (const char*)(gWt + (size_t)colBase * DDIM) + c * 128;
        #pragma unroll
        for (int i = 0; i < 4; ++i) {
            int g = tid + i * 256;
            int r = g >> 3, gi = g & 7;
            uint32_t d = r * 128 + ((gi * 16) ^ ((r & 7) << 4));
            cpa16(sb + offA[stg] + d, As + (size_t)r * 1024 + gi * 16);
        }
        #pragma unroll
        for (int i = 0; i < 4; ++i) {
            int g = tid + i * 256;
            int n = g >> 3, gi = g & 7;
            uint32_t d = n * 128 + ((gi * 16) ^ ((n & 7) << 4));
            cpa16(sb + offB[stg] + d, Bs + (size_t)n * 1024 + gi * 16);
        }
        CP_COMMIT();
    };

    uint32_t baseA[4], patA[4];
    #pragma unroll
    for (int mi = 0; mi < 4; ++mi) {
        int r = wm * 64 + mi * 16 + (lane & 15);
        baseA[mi] = r * 128;
        patA[mi]  = (r & 7) << 4;
    }
    const uint32_t aQuad = (lane >> 4) * 16;
    uint32_t baseB[2], patB[2];
    #pragma unroll
    for (int bi = 0; bi < 2; ++bi) {
        int n = wn * 32 + bi * 16 + (lane & 7) + ((lane >> 4) << 3);
        baseB[bi] = n * 128;
        patB[bi]  = (n & 7) << 4;
    }
    const uint32_t bQuad = ((lane >> 3) & 1) * 16;

    float acc[4][4][4];
    #pragma unroll
    for (int a = 0; a < 4; ++a)
        #pragma unroll
        for (int b = 0; b < 4; ++b)
            #pragma unroll
            for (int q = 0; q < 4; ++q) acc[a][b][q] = 0.f;

    load_chunk(0, 0);
    load_chunk(1, 1);

    #pragma unroll
    for (int c = 0; c < 8; ++c) {
        if (c == 7) { CP_WAIT(0); } else { CP_WAIT(1); }
        __syncthreads();
        if (c + 2 < 8) load_chunk(c + 2, (c + 2) % 3);

        const uint32_t aBuf = sb + offA[c % 3];
        const uint32_t bBuf = sb + offB[c % 3];
        #pragma unroll
        for (int kk = 0; kk < 4; ++kk) {
            const uint32_t kb = kk * 32;
            uint32_t af[4][4], bf[2][4];
            #pragma unroll
            for (int mi = 0; mi < 4; ++mi)
                ldsm_x4(aBuf + baseA[mi] + ((kb + aQuad) ^ patA[mi]), af[mi]);
            #pragma unroll
            for (int bi = 0; bi < 2; ++bi)
                ldsm_x4(bBuf + baseB[bi] + ((kb + bQuad) ^ patB[bi]), bf[bi]);
            #pragma unroll
            for (int mi = 0; mi < 4; ++mi)
                #pragma unroll
                for (int bi = 0; bi < 2; ++bi) {
                    mma_bf16(acc[mi][bi * 2 + 0], af[mi], bf[bi][0], bf[bi][1]);
                    mma_bf16(acc[mi][bi * 2 + 1], af[mi], bf[bi][2], bf[bi][3]);
                }
        }
    }

    // ---- epilogue: per-(row, 8col-group) d2 mins -> gGmin ----
    const int tig = lane & 3;
    const int g   = lane >> 2;
    float gm0[4][4], gm1[4][4];
    #pragma unroll
    for (int mi = 0; mi < 4; ++mi) {
        const int r0 = wm * 64 + mi * 16 + g;
        const int r1 = r0 + 8;
        const float rr0 = sRow[r0], rr1 = sRow[r1];
        #pragma unroll
        for (int j = 0; j < 4; ++j) {
            const int cb = wn * 32 + j * 8 + 2 * tig;
            const float cc0 = sCol[cb], cc1 = sCol[cb + 1];
            float m0 = fminf(rr0 + cc0 - 2.f * acc[mi][j][0],
                             rr0 + cc1 - 2.f * acc[mi][j][1]);
            float m1 = fminf(rr1 + cc0 - 2.f * acc[mi][j][2],
                             rr1 + cc1 - 2.f * acc[mi][j][3]);
            m0 = fminf(m0, __shfl_xor_sync(0xFFFFFFFFu, m0, 1));
            m0 = fminf(m0, __shfl_xor_sync(0xFFFFFFFFu, m0, 2));
            m1 = fminf(m1, __shfl_xor_sync(0xFFFFFFFFu, m1, 1));
            m1 = fminf(m1, __shfl_xor_sync(0xFFFFFFFFu, m1, 2));
            gm0[mi][j] = m0;
            gm1[mi][j] = m1;
        }
    }
    if (tig == 0) {
        const int gcol = blockIdx.x * 16 + wn * 4;
        #pragma unroll
        for (int mi = 0; mi < 4; ++mi) {
            const int r0 = rowBase + wm * 64 + mi * 16 + g;
            const int r1 = r0 + 8;
            __half2 a0 = __floats2half2_rn(gm0[mi][0], gm0[mi][1]);
            __half2 a1 = __floats2half2_rn(gm0[mi][2], gm0[mi][3]);
            __half2 b0 = __floats2half2_rn(gm1[mi][0], gm1[mi][1]);
            __half2 b1 = __floats2half2_rn(gm1[mi][2], gm1[mi][3]);
            uint2 v0, v1;
            v0.x = *(uint32_t*)&a0; v0.y = *(uint32_t*)&a1;
            v1.x = *(uint32_t*)&b0; v1.y = *(uint32_t*)&b1;
            *(uint2*)(gGmin + (size_t)r0 * NGRP + gcol) = v0;
            *(uint2*)(gGmin + (size_t)r1 * NGRP + gcol) = v1;
        }
    }
}

// ------- refine: group-min scan -> qualifying groups -> exact fp32 dots -------
__global__ void refine_kernel(const float* __restrict__ X,
                              const float* __restrict__ loc,
                              float* __restrict__ out, int out_size) {
    const int b = blockIdx.x;
    const int tid = threadIdx.x;
    const int wid = tid >> 5;
    const int lane = tid & 31;
    __shared__ unsigned sMin;
    __shared__ int cnt;
    __shared__ int grp[256];
    __shared__ unsigned long long wbest[8];
    if (tid == 0) { sMin = 0x7F800000u; cnt = 0; }
    __syncthreads();

    const uint4 v = ((const uint4*)(gGmin + (size_t)b * NGRP))[tid];
    const uint32_t ww[4] = {v.x, v.y, v.z, v.w};
    float h[8];
    #pragma unroll
    for (int q = 0; q < 4; ++q) {
        __half2 p = *(const __half2*)&ww[q];
        h[2 * q]     = __low2float(p);
        h[2 * q + 1] = __high2float(p);
    }
    float m = h[0];
    #pragma unroll
    for (int q = 1; q < 8; ++q) m = fminf(m, h[q]);
    #pragma unroll
    for (int o = 16; o; o >>= 1) m = fminf(m, __shfl_sync(0xFFFFFFFFu, m, lane ^ o));
    if (lane == 0) atomicMin(&sMin, __float_as_uint(m));
    __syncthreads();

    const float thr = __uint_as_float(sMin) + DELTA;
    #pragma unroll
    for (int q = 0; q < 8; ++q)
        if (h[q] <= thr) { int p = atomicAdd(&cnt, 1); if (p < 256) grp[p] = tid * 8 + q; }
    __syncthreads();
    const int ng = min(cnt, 256);
    const int ncand = ng * 8;

    const float4* xr = (const float4*)(X + (size_t)b * DDIM);
    float4 xv[4];
    #pragma unroll
    for (int i = 0; i < 4; ++i) xv[i] = xr[i * 32 + lane];

    unsigned long long best = 0xFFFFFFFFFFFFFFFFULL;
    for (int ci = wid; ci < ncand; ci += 8) {
        const int k = grp[ci >> 3] * 8 + (ci & 7);
        const float4* wr = (const float4*)(gWt32 + (size_t)k * DDIM);
        float s = 0.f;
        #pragma unroll
        for (int i = 0; i < 4; ++i) {
            float4 w = wr[i * 32 + lane];
            s = fmaf(xv[i].x, w.x, s);
            s = fmaf(xv[i].y, w.y, s);
            s = fmaf(xv[i].z, w.z, s);
            s = fmaf(xv[i].w, w.w, s);
        }
        #pragma unroll
        for (int o = 16; o; o >>= 1) s += __shfl_xor_sync(0xFFFFFFFFu, s, o);
        if (lane == 0) {
            float d2 = g_r[b] + g_c[k] - 2.f * s;
            unsigned u = __float_as_uint(d2);
            u = (u & 0x80000000u) ? ~u : (u | 0x80000000u);
            unsigned long long key = ((unsigned long long)u << 32) | (unsigned)k;
            if (key < best) best = key;
        }
    }
    if (lane == 0) wbest[wid] = best;
    __syncthreads();

    if (tid == 0) {
        unsigned long long bb = 0xFFFFFFFFFFFFFFFFULL;
        #pragma unroll
        for (int w = 0; w < 8; ++w) if (wbest[w] < bb) bb = wbest[w];
        unsigned k = (unsigned)(bb & 0xFFFFFFFFu);
        unsigned u = (unsigned)(bb >> 32);
        u = (u & 0x80000000u) ? (u & 0x7FFFFFFFu) : ~u;
        float d2 = __uint_as_float(u);
        g_dist[b] = sqrtf(fmaxf(d2, 0.f));
        out[2 * b] = loc[2 * k];
        if (2 * b + 1 < out_size - 1) out[2 * b + 1] = loc[2 * k + 1];
    }
}

__global__ void loss_kernel(float* __restrict__ out, int out_size) {
    __shared__ float sh[1024];
    float local = 0.f;
    for (int b = threadIdx.x; b < B_ROWS; b += 1024) local += g_dist[b];
    sh[threadIdx.x] = local;
    __syncthreads();
    #pragma unroll
    for (int s = 512; s > 0; s >>= 1) {
        if (threadIdx.x < s) sh[threadIdx.x] += sh[threadIdx.x + s];
        __syncthreads();
    }
    if (threadIdx.x == 0) out[out_size - 1] = sh[0] / (float)B_ROWS;
}

// ---------------------------------------------------------------------------
extern "C" void kernel_launch(void* const* d_in, const int* in_sizes, int n_in,
                              void* d_out, int out_size) {
    const float* X = (const float*)d_in[0];  // (4096, 512)
    const float* W = (const float*)d_in[1];  // (512, 16384)
    const float* L = (const float*)d_in[2];  // (16384, 2)
    float* out = (float*)d_out;

    cudaFuncSetAttribute(gemm_kernel, cudaFuncAttributeMaxDynamicSharedMemorySize, SMEM_TOT);

    prep_kernel<<<8192 + B_ROWS / 2, 256>>>(X, W);
    col_finalize_kernel<<<KN / 256, 256>>>();

    gemm_kernel<<<dim3(KN / 128, B_ROWS / 128), 256, SMEM_TOT>>>();

    refine_kernel<<<B_ROWS, 256>>>(X, L, out, out_size);
    loss_kernel<<<1, 1024>>>(out, out_size);
}